// round 17
// baseline (speedup 1.0000x reference)
#include <cuda_runtime.h>

#define NN 65536
#define HH 64

typedef unsigned long long ull;
typedef unsigned int u32;

// ---- packed f32x2 helpers (Blackwell FFMA2 path; 2x FP32 FMA throughput) ----
__device__ __forceinline__ ull dup2(float a) {
    ull r; asm("mov.b64 %0, {%1,%1};" : "=l"(r) : "f"(a)); return r;
}
__device__ __forceinline__ ull pk2(float a, float b) {
    ull r; asm("mov.b64 %0, {%1,%2};" : "=l"(r) : "f"(a), "f"(b)); return r;
}
__device__ __forceinline__ float2 up2(ull a) {
    float x, y; asm("mov.b64 {%0,%1}, %2;" : "=f"(x), "=f"(y) : "l"(a));
    return make_float2(x, y);
}
__device__ __forceinline__ ull f2fma(ull a, ull b, ull c) {
    ull d; asm("fma.rn.f32x2 %0, %1, %2, %3;" : "=l"(d) : "l"(a), "l"(b), "l"(c));
    return d;
}
__device__ __forceinline__ ull f2add(ull a, ull b) {
    ull d; asm("add.rn.f32x2 %0, %1, %2;" : "=l"(d) : "l"(a), "l"(b));
    return d;
}

// scratch (static device array: allowed; no runtime allocation)
__device__ float g_out[NN * HH];   // aggregated node features + residual

// ============================================================================
// Kernel 1: fused message + single-pass softmax + weighted aggregate + residual
// warp per node; lane l owns channels (2l, 2l+1).
// FFMA2 SIMD axis = d-PAIR (not channel-pair): the packed multiplier
// (ea[2i], ea[2i+1]) comes straight out of the staged smem row via LDS.128 —
// ZERO per-FMA dup MOVs. Weights repacked once per warp:
//   w0[i] = (W[2i][c0], W[2i+1][c0]),  w1[i] = same for c1.
// Accumulators are (even-d, odd-d) partial pairs; horizontal add + x residual
// folds in 2 FADD per channel per edge.
// ============================================================================
__global__ void __launch_bounds__(256, 3) k_msg(
    const float* __restrict__ x, const float* __restrict__ ea,
    const float* __restrict__ We, const int* __restrict__ srcIdx)
{
    __shared__ float4 sEA[8][64];   // 8 warps x 1KB

    int t = threadIdx.x;
    int l = t & 31;
    int wid = t >> 5;
    int n = (blockIdx.x << 3) + wid;

    // stage ea[node] (1KB) via cp.async: 2 x 16B per lane
    {
        const float4* easrc = (const float4*)(ea + (size_t)n * 256);
        u32 dst = (u32)__cvta_generic_to_shared(&sEA[wid][l]);
        asm volatile("cp.async.ca.shared.global [%0], [%1], 16;\n"
                     :: "r"(dst), "l"(easrc + l));
        asm volatile("cp.async.ca.shared.global [%0], [%1], 16;\n"
                     :: "r"(dst + 512), "l"(easrc + l + 32));
        asm volatile("cp.async.commit_group;\n");
    }

    // load W_edge pairs (W[d][2l], W[d][2l+1]) then repack along d:
    // w0[i] = (W[2i][2l],   W[2i+1][2l])
    // w1[i] = (W[2i][2l+1], W[2i+1][2l+1])
    const ull* We2 = (const ull*)We;
    ull w0[8], w1[8];
    #pragma unroll
    for (int i = 0; i < 8; i++) {
        float2 wa = up2(__ldg(We2 + (2 * i)     * 32 + l));
        float2 wb = up2(__ldg(We2 + (2 * i + 1) * 32 + l));
        w0[i] = pk2(wa.x, wb.x);
        w1[i] = pk2(wa.y, wb.y);
    }

    const ull* x2 = (const ull*)x;
    const int4* sidx = (const int4*)(srcIdx + n * 16);

    // batch A: edges 0..7
    int4 s0 = __ldg(sidx + 0), s1 = __ldg(sidx + 1);
    int seA[8] = { s0.x, s0.y, s0.z, s0.w,  s1.x, s1.y, s1.z, s1.w };
    ull xgA[8];
    #pragma unroll
    for (int k = 0; k < 8; k++)
        xgA[k] = __ldg(x2 + (size_t)seA[k] * 32 + l);

    // batch B: edges 8..15
    int4 s2 = __ldg(sidx + 2), s3 = __ldg(sidx + 3);
    int seB[8] = { s2.x, s2.y, s2.z, s2.w,  s3.x, s3.y, s3.z, s3.w };
    ull xgB[8];
    #pragma unroll
    for (int k = 0; k < 8; k++)
        xgB[k] = __ldg(x2 + (size_t)seB[k] * 32 + l);

    ull xres = __ldg(x2 + (size_t)n * 32 + l);

    asm volatile("cp.async.wait_group 0;\n");
    __syncwarp();

    const ulonglong2* av2 = (const ulonglong2*)sEA[wid];
    float den0 = 0.0f, den1 = 0.0f, num0 = 0.0f, num1 = 0.0f;

    #pragma unroll
    for (int half = 0; half < 2; half++) {
        #pragma unroll
        for (int kk = 0; kk < 8; kk++) {
            int k = half * 8 + kk;
            // 4 x LDS.128 -> 8 packed d-pairs, ready as FFMA2 operands
            ulonglong2 p0 = av2[4 * k + 0], p1 = av2[4 * k + 1];
            ulonglong2 p2 = av2[4 * k + 2], p3 = av2[4 * k + 3];
            ull eap[8] = { p0.x, p0.y, p1.x, p1.y, p2.x, p2.y, p3.x, p3.y };

            ull a0 = 0ULL, a1 = 0ULL;
            #pragma unroll
            for (int i = 0; i < 8; i++) {
                a0 = f2fma(eap[i], w0[i], a0);
                a1 = f2fma(eap[i], w1[i], a1);
            }

            float2 A0 = up2(a0), A1 = up2(a1);   // free (register pair halves)
            float2 xv = up2((half == 0) ? xgA[kk] : xgB[kk]);
            float m0 = (A0.x + A0.y) + xv.x;
            float m1 = (A1.x + A1.y) + xv.y;
            m0 = fmaxf(m0, 0.0f) + 1e-7f;
            m1 = fmaxf(m1, 0.0f) + 1e-7f;
            float e0 = __expf(m0), e1 = __expf(m1);
            den0 += e0;  den1 += e1;
            num0 = fmaf(m0, e0, num0);
            num1 = fmaf(m1, e1, num1);
        }
    }

    float2 xn = up2(xres);
    float o0 = __fdividef(num0, den0 + 1e-16f) + xn.x;
    float o1 = __fdividef(num1, den1 + 1e-16f) + xn.y;
    ((float2*)g_out)[n * 32 + l] = make_float2(o0, o1);
}

// ============================================================================
// Kernel 2: FUSED MLP  y = relu(BN(out @ W1)) @ W2 — two GEMM stages through
// shared memory, no g_h global round-trip. (unchanged — 58.3us passing)
// ============================================================================
__global__ void __launch_bounds__(256, 2) k_mlp(
    const float* __restrict__ W1, const float* __restrict__ W2,
    const float* __restrict__ gamma, const float* __restrict__ beta,
    const float* __restrict__ mean, const float* __restrict__ var,
    float* __restrict__ y)
{
    extern __shared__ ull smF[];
    ull*   sW1 = smF;                      // 32 KB
    ull*   sS  = smF + 4096;               // 64 jpairs
    ull*   sB  = smF + 4160;               // 64 jpairs
    float* sO  = (float*)(smF + 4224);     // 32 KB  [64 c][128 node]
    ull*   sW2 = smF + 8320;               // 32 KB  [128 j][32 cpair]
    float* sH  = (float*)smF;              // 64 KB  [128 j][128 node] (overlay)

    int t  = threadIdx.x;
    int nb = blockIdx.x * 128;

    {
        const ulonglong2* w1v = (const ulonglong2*)W1;
        const ulonglong2* w2v = (const ulonglong2*)W2;
        ulonglong2* d1 = (ulonglong2*)sW1;
        ulonglong2* d2 = (ulonglong2*)sW2;
        #pragma unroll
        for (int i = 0; i < 8; i++) {
            d1[t + 256 * i] = __ldg(w1v + t + 256 * i);
            d2[t + 256 * i] = __ldg(w2v + t + 256 * i);
        }
    }
    if (t < 64) {
        float s0 = __ldg(gamma + 2 * t)     * rsqrtf(__ldg(var + 2 * t)     + 1e-5f);
        float s1 = __ldg(gamma + 2 * t + 1) * rsqrtf(__ldg(var + 2 * t + 1) + 1e-5f);
        sS[t] = pk2(s0, s1);
        sB[t] = pk2(__ldg(beta + 2 * t)     - __ldg(mean + 2 * t)     * s0,
                    __ldg(beta + 2 * t + 1) - __ldg(mean + 2 * t + 1) * s1);
    }
    {
        int n  = t & 127;
        int ch = (t >> 7) * 32;
        const float4* src = (const float4*)(g_out + (size_t)(nb + n) * 64 + ch);
        #pragma unroll
        for (int i = 0; i < 8; i++) {
            float4 v = __ldg(src + i);
            int c = ch + 4 * i;
            sO[(c + 0) * 128 + n] = v.x;
            sO[(c + 1) * 128 + n] = v.y;
            sO[(c + 2) * 128 + n] = v.z;
            sO[(c + 3) * 128 + n] = v.w;
        }
    }
    __syncthreads();

    int m = t & 31;
    int g = t >> 5;

    ull acc[32];
    #pragma unroll
    for (int p = 0; p < 32; p++) acc[p] = 0ULL;

    #pragma unroll 8
    for (int c = 0; c < 64; c++) {
        float4 a4 = *(const float4*)(sO + c * 128 + m * 4);
        const ulonglong2* bp = (const ulonglong2*)(sW1 + c * 64 + g * 8);
        ulonglong2 b0 = bp[0], b1 = bp[1], b2 = bp[2], b3 = bp[3];
        ull wr[8] = { b0.x, b0.y, b1.x, b1.y, b2.x, b2.y, b3.x, b3.y };
        ull ad0 = dup2(a4.x), ad1 = dup2(a4.y), ad2 = dup2(a4.z), ad3 = dup2(a4.w);
        #pragma unroll
        for (int p = 0; p < 8; p++) {
            acc[p]      = f2fma(ad0, wr[p], acc[p]);
            acc[8 + p]  = f2fma(ad1, wr[p], acc[8 + p]);
            acc[16 + p] = f2fma(ad2, wr[p], acc[16 + p]);
            acc[24 + p] = f2fma(ad3, wr[p], acc[24 + p]);
        }
    }

    #pragma unroll
    for (int mm = 0; mm < 4; mm++) {
        #pragma unroll
        for (int q = 0; q < 8; q++) {
            ull hb = f2fma(acc[mm * 8 + q], sS[g * 8 + q], sB[g * 8 + q]);
            float2 hv = up2(hb);
            acc[mm * 8 + q] = pk2(fmaxf(hv.x, 0.0f), fmaxf(hv.y, 0.0f));
        }
    }
    __syncthreads();

    #pragma unroll
    for (int q = 0; q < 8; q++) {
        float2 h0 = up2(acc[0 * 8 + q]);
        float2 h1 = up2(acc[1 * 8 + q]);
        float2 h2 = up2(acc[2 * 8 + q]);
        float2 h3 = up2(acc[3 * 8 + q]);
        *(float4*)(sH + (g * 16 + 2 * q)     * 128 + m * 4) =
            make_float4(h0.x, h1.x, h2.x, h3.x);
        *(float4*)(sH + (g * 16 + 2 * q + 1) * 128 + m * 4) =
            make_float4(h0.y, h1.y, h2.y, h3.y);
    }
    __syncthreads();

    ull acc2[16];
    #pragma unroll
    for (int p = 0; p < 16; p++) acc2[p] = 0ULL;

    #pragma unroll 8
    for (int k = 0; k < 128; k++) {
        float4 a4 = *(const float4*)(sH + k * 128 + m * 4);
        const ulonglong2* bp = (const ulonglong2*)(sW2 + k * 32 + g * 4);
        ulonglong2 b0 = bp[0], b1 = bp[1];
        ull wr[4] = { b0.x, b0.y, b1.x, b1.y };
        ull ad0 = dup2(a4.x), ad1 = dup2(a4.y), ad2 = dup2(a4.z), ad3 = dup2(a4.w);
        #pragma unroll
        for (int p = 0; p < 4; p++) {
            acc2[p]      = f2fma(ad0, wr[p], acc2[p]);
            acc2[4 + p]  = f2fma(ad1, wr[p], acc2[4 + p]);
            acc2[8 + p]  = f2fma(ad2, wr[p], acc2[8 + p]);
            acc2[12 + p] = f2fma(ad3, wr[p], acc2[12 + p]);
        }
    }

    #pragma unroll
    for (int mm = 0; mm < 4; mm++) {
        ulonglong2* dst =
            (ulonglong2*)(y + (size_t)(nb + m * 4 + mm) * 64 + g * 8);
        dst[0] = make_ulonglong2(acc2[mm * 4 + 0], acc2[mm * 4 + 1]);
        dst[1] = make_ulonglong2(acc2[mm * 4 + 2], acc2[mm * 4 + 3]);
    }
}

// ============================================================================
extern "C" void kernel_launch(void* const* d_in, const int* in_sizes, int n_in,
                              void* d_out, int out_size)
{
    const float* x     = (const float*)d_in[0];
    const float* ea    = (const float*)d_in[1];
    const float* We    = (const float*)d_in[2];
    const float* W1    = (const float*)d_in[3];
    const float* W2    = (const float*)d_in[4];
    const float* gamma = (const float*)d_in[5];
    const float* beta  = (const float*)d_in[6];
    const float* mean  = (const float*)d_in[7];
    const float* var   = (const float*)d_in[8];
    const int*   eidx  = (const int*)d_in[9];   // row 0 = src
    float* y = (float*)d_out;

    (void)in_sizes; (void)n_in; (void)out_size;

    const int SMEM = 12416 * 8;   // 99328 B
    cudaFuncSetAttribute(k_mlp, cudaFuncAttributeMaxDynamicSharedMemorySize,
                         SMEM);

    k_msg<<<NN / 8, 256>>>(x, ea, We, eidx);
    k_mlp<<<NN / 128, 256, SMEM>>>(W1, W2, gamma, beta, mean, var, y);
}